// round 14
// baseline (speedup 1.0000x reference)
#include <cuda_runtime.h>
#include <cstdint>
#include <cstddef>

// ---------------------------------------------------------------------------
// PolicyHead round 13:
//   logits = out@M@out^T + u.out_i + v.out_j + s0,  M = W2^T W3 (precomputed)
//   gemm1 : out = relu(x@W1^T+b1)        (proven 255us)
//   gemmT : tmp = out @ Mt^T             (NEW: gemm1-shaped, all-uint2 frags)
//   attf  : logits from tmp/outs + rank-1 + promo + gather (phase-2 only)
// ---------------------------------------------------------------------------

#define HDIM 256
#define MROWS 262144
#define PSCALE 0.0625f

__device__ unsigned g_out[(size_t)MROWS * HDIM];
__device__ unsigned g_tmp[(size_t)MROWS * HDIM];
__device__ unsigned g_w1[HDIM * HDIM];     // tf32 bits, perm'd k
__device__ unsigned g_mt[HDIM * HDIM];     // Mt[c,a], tf32, perm on a
__device__ float    g_u[HDIM];             // perm-indexed
__device__ float    g_v[HDIM];             // perm-indexed
__device__ float    g_wp[4 * HDIM];        // perm-indexed
__device__ float    g_misc[8];             // [0]=s0, [1..4]=d0[p]

__device__ __forceinline__ unsigned f2tf(float f) {
    unsigned r;
    asm("cvt.rna.tf32.f32 %0, %1;" : "=r"(r) : "f"(f));
    return r;
}
__device__ __forceinline__ int perm(int c) {
    return (c & ~7) | ((c & 3) << 1) | ((c >> 2) & 1);
}
__device__ __forceinline__ void mma8(float* d, const unsigned* a, const unsigned* b) {
    asm volatile(
        "mma.sync.aligned.m16n8k8.row.col.f32.tf32.tf32.f32 "
        "{%0,%1,%2,%3}, {%4,%5,%6,%7}, {%8,%9}, {%0,%1,%2,%3};\n"
        : "+f"(d[0]), "+f"(d[1]), "+f"(d[2]), "+f"(d[3])
        : "r"(a[0]), "r"(a[1]), "r"(a[2]), "r"(a[3]), "r"(b[0]), "r"(b[1]));
}
__device__ __forceinline__ unsigned sptr(const void* p) {
    return (unsigned)__cvta_generic_to_shared(p);
}
__device__ __forceinline__ void cpa16(unsigned s, const void* g) {
    asm volatile("cp.async.ca.shared.global [%0], [%1], 16;" :: "r"(s), "l"(g));
}
#define CPA_COMMIT asm volatile("cp.async.commit_group;")
#define CPA_WAIT(n) asm volatile("cp.async.wait_group %0;" :: "n"(n))

// ---------------------------------------------------------------------------
__global__ void prep_w1_kernel(const float* __restrict__ w1) {
    int i = blockIdx.x * 256 + threadIdx.x;
    int row = i >> 8, col = i & 255;
    g_w1[row * HDIM + perm(col)] = f2tf(w1[i]);
}

__global__ __launch_bounds__(256)
void prepM_kernel(const float* __restrict__ w2, const float* __restrict__ w3) {
    extern __shared__ float s[];
    float* s2 = s;               // [256][68]
    float* s3 = s + 256 * 68;
    const int a0 = (blockIdx.x & 3) * 64, c0 = (blockIdx.x >> 2) * 64;
    const int tid = threadIdx.x;
    for (int j = tid; j < 256 * 16; j += 256) {
        int h = j >> 4, q4 = (j & 15) << 2;
        *(float4*)&s2[h * 68 + q4] = *(const float4*)(w2 + h * HDIM + a0 + q4);
        *(float4*)&s3[h * 68 + q4] = *(const float4*)(w3 + h * HDIM + c0 + q4);
    }
    __syncthreads();
    const int tx = tid & 15, ty = tid >> 4;
    float acc[4][4] = {};
    for (int h = 0; h < 256; h++) {
        float4 av = *(float4*)&s2[h * 68 + tx * 4];
        float4 cv = *(float4*)&s3[h * 68 + ty * 4];
        float aa[4] = {av.x, av.y, av.z, av.w};
        float cc[4] = {cv.x, cv.y, cv.z, cv.w};
#pragma unroll
        for (int i = 0; i < 4; i++)
#pragma unroll
            for (int j = 0; j < 4; j++) acc[i][j] += cc[i] * aa[j];
    }
#pragma unroll
    for (int i = 0; i < 4; i++)
#pragma unroll
        for (int j = 0; j < 4; j++)
            g_mt[(c0 + ty * 4 + i) * HDIM + perm(a0 + tx * 4 + j)] = f2tf(acc[i][j]);
}

__global__ void prepv_kernel(const float* __restrict__ w2, const float* __restrict__ b2,
                             const float* __restrict__ w3, const float* __restrict__ b3,
                             const float* __restrict__ w4) {
    int a = threadIdx.x;
    float u = 0.f, v = 0.f, p0 = 0.f, p1 = 0.f, p2 = 0.f, p3 = 0.f;
    for (int h = 0; h < 256; h++) {
        float w2v = w2[h * HDIM + a], w3v = w3[h * HDIM + a];
        u += w2v * b3[h];
        v += b2[h] * w3v;
        p0 += w3v * w4[0 * HDIM + h];
        p1 += w3v * w4[1 * HDIM + h];
        p2 += w3v * w4[2 * HDIM + h];
        p3 += w3v * w4[3 * HDIM + h];
    }
    int pa = perm(a);
    g_u[pa] = u; g_v[pa] = v;
    g_wp[0 * HDIM + pa] = p0; g_wp[1 * HDIM + pa] = p1;
    g_wp[2 * HDIM + pa] = p2; g_wp[3 * HDIM + pa] = p3;
    if (a == 0) {
        float s = 0.f;
        for (int h = 0; h < 256; h++) s += b2[h] * b3[h];
        g_misc[0] = s;
    }
    if (a >= 1 && a <= 4) {
        float d = 0.f;
        for (int h = 0; h < 256; h++) d += b3[h] * w4[(a - 1) * HDIM + h];
        g_misc[a] = d;
    }
}

// ---------------------------------------------------------------------------
// GEMM1 (round-5, proven 255us): out = relu(x @ W1^T + b1).
// ---------------------------------------------------------------------------
constexpr int GSA = 36;
constexpr int GSB = 40;

__global__ __launch_bounds__(256, 2)
void gemm1_kernel(const float* __restrict__ A, const float* __restrict__ bias,
                  unsigned* __restrict__ C) {
    extern __shared__ unsigned sh[];
    unsigned* sA = sh;
    unsigned* sB = sh + 2 * 128 * GSA;
    const int m0 = blockIdx.y * 128, n0 = blockIdx.x * 128;
    const int tid = threadIdx.x;
    const int warp = tid >> 5, lane = tid & 31, g = lane >> 2, t = lane & 3;
    const int wm = warp >> 1, wn = warp & 1;

    float acc[2][8][4];
#pragma unroll
    for (int i = 0; i < 2; i++)
#pragma unroll
        for (int j = 0; j < 8; j++)
#pragma unroll
            for (int l = 0; l < 4; l++) acc[i][j][l] = 0.f;

    const int lrow = tid >> 3, lc4 = (tid & 7) << 2;

#pragma unroll
    for (int i = 0; i < 4; i++) {
        int row = lrow + i * 32;
        cpa16(sptr(&sA[row * GSA + lc4]), A + (size_t)(m0 + row) * HDIM + lc4);
        cpa16(sptr(&sB[row * GSB + lc4]), g_w1 + (size_t)(n0 + row) * HDIM + lc4);
    }
    CPA_COMMIT;

    for (int c = 0; c < 8; c++) {
        int cur = c & 1;
        if (c < 7) {
            int nx = cur ^ 1, k0 = (c + 1) * 32;
#pragma unroll
            for (int i = 0; i < 4; i++) {
                int row = lrow + i * 32;
                cpa16(sptr(&sA[nx * 128 * GSA + row * GSA + lc4]),
                      A + (size_t)(m0 + row) * HDIM + k0 + lc4);
                cpa16(sptr(&sB[nx * 128 * GSB + row * GSB + lc4]),
                      g_w1 + (size_t)(n0 + row) * HDIM + k0 + lc4);
            }
            CPA_COMMIT;
            CPA_WAIT(1);
        } else {
            CPA_WAIT(0);
        }
        __syncthreads();
        const unsigned* As = &sA[cur * 128 * GSA];
        const unsigned* Bs = &sB[cur * 128 * GSB];
#pragma unroll
        for (int ks = 0; ks < 32; ks += 8) {
            unsigned a[2][4];
#pragma unroll
            for (int mi = 0; mi < 2; mi++) {
                int r = wm * 32 + mi * 16;
                a[mi][0] = f2tf(__uint_as_float(As[(r + g) * GSA + ks + t]));
                a[mi][1] = f2tf(__uint_as_float(As[(r + g + 8) * GSA + ks + t]));
                a[mi][2] = f2tf(__uint_as_float(As[(r + g) * GSA + ks + t + 4]));
                a[mi][3] = f2tf(__uint_as_float(As[(r + g + 8) * GSA + ks + t + 4]));
            }
#pragma unroll
            for (int ni = 0; ni < 8; ni++) {
                int cc = wn * 64 + ni * 8;
                uint2 bv = *(const uint2*)&Bs[(cc + g) * GSB + ks + 2 * t];
                unsigned bb[2] = {bv.x, bv.y};
                mma8(acc[0][ni], a[0], bb);
                mma8(acc[1][ni], a[1], bb);
            }
        }
        __syncthreads();
    }
#pragma unroll
    for (int mi = 0; mi < 2; mi++)
#pragma unroll
        for (int h = 0; h < 2; h++) {
            int r = m0 + wm * 32 + mi * 16 + g + h * 8;
#pragma unroll
            for (int ni = 0; ni < 8; ni++) {
                int cc = n0 + wn * 64 + ni * 8 + 2 * t;
                float v0 = fmaxf(acc[mi][ni][h * 2 + 0] + bias[cc], 0.f);
                float v1 = fmaxf(acc[mi][ni][h * 2 + 1] + bias[cc + 1], 0.f);
                C[(size_t)r * HDIM + perm(cc)]     = f2tf(v0);
                C[(size_t)r * HDIM + perm(cc + 1)] = f2tf(v1);
            }
        }
}

// ---------------------------------------------------------------------------
// gemmT: tmp = out @ Mt^T. gemm1 structure; both operands pre-tf32+perm ->
// all-uint2 fragments, zero cvt inner loop. Packed XOR-swizzled smem (64KB).
// ---------------------------------------------------------------------------
__global__ __launch_bounds__(256, 2)
void gemmT_kernel(unsigned* __restrict__ T) {
    extern __shared__ unsigned sh[];
    unsigned* sA = sh;           // 2 x 128x32 packed
    unsigned* sB = sh + 8192;    // 2 x 128x32 packed
    const int m0 = blockIdx.y * 128, n0 = blockIdx.x * 128;
    const int tid = threadIdx.x;
    const int warp = tid >> 5, lane = tid & 31, g = lane >> 2, t = lane & 3;
    const int wm = warp >> 1, wn = warp & 1;
    const int sw = (g & 3) << 3;

    float acc[2][8][4];
#pragma unroll
    for (int i = 0; i < 2; i++)
#pragma unroll
        for (int j = 0; j < 8; j++)
#pragma unroll
            for (int l = 0; l < 4; l++) acc[i][j][l] = 0.f;

#pragma unroll
    for (int i = 0; i < 4; i++) {
        int e = tid + i * 256;
        int row = e >> 3, c4 = (e & 7) << 2;
        int d = row * 32 + (c4 ^ ((row & 3) << 3));
        cpa16(sptr(&sA[d]), g_out + (size_t)(m0 + row) * HDIM + c4);
        cpa16(sptr(&sB[d]), g_mt + (size_t)(n0 + row) * HDIM + c4);
    }
    CPA_COMMIT;

    for (int c = 0; c < 8; c++) {
        int cur = c & 1;
        if (c < 7) {
            int nx = cur ^ 1, k0 = (c + 1) * 32;
#pragma unroll
            for (int i = 0; i < 4; i++) {
                int e = tid + i * 256;
                int row = e >> 3, c4 = (e & 7) << 2;
                int d = nx * 4096 + row * 32 + (c4 ^ ((row & 3) << 3));
                cpa16(sptr(&sA[d]), g_out + (size_t)(m0 + row) * HDIM + k0 + c4);
                cpa16(sptr(&sB[d]), g_mt + (size_t)(n0 + row) * HDIM + k0 + c4);
            }
            CPA_COMMIT;
            CPA_WAIT(1);
        } else {
            CPA_WAIT(0);
        }
        __syncthreads();
        const unsigned* As = &sA[cur * 4096];
        const unsigned* Bs = &sB[cur * 4096];
#pragma unroll
        for (int ks = 0; ks < 32; ks += 8) {
            unsigned a[2][4];
#pragma unroll
            for (int mi = 0; mi < 2; mi++) {
                int r = wm * 32 + mi * 16 + g;
                uint2 a0 = *(const uint2*)&As[r * 32 + ((ks + 2 * t) ^ sw)];
                uint2 a1 = *(const uint2*)&As[(r + 8) * 32 + ((ks + 2 * t) ^ sw)];
                a[mi][0] = a0.x; a[mi][1] = a1.x; a[mi][2] = a0.y; a[mi][3] = a1.y;
            }
#pragma unroll
            for (int ni = 0; ni < 8; ni++) {
                int cb = wn * 64 + ni * 8 + g;
                uint2 bv = *(const uint2*)&Bs[cb * 32 + ((ks + 2 * t) ^ sw)];
                unsigned bb[2] = {bv.x, bv.y};
                mma8(acc[0][ni], a[0], bb);
                mma8(acc[1][ni], a[1], bb);
            }
        }
        __syncthreads();
    }
    // epilogue: tf32 + perm store (no bias, no relu)
#pragma unroll
    for (int mi = 0; mi < 2; mi++)
#pragma unroll
        for (int h = 0; h < 2; h++) {
            int r = m0 + wm * 32 + mi * 16 + g + h * 8;
#pragma unroll
            for (int ni = 0; ni < 8; ni++) {
                int cc = n0 + wn * 64 + ni * 8 + 2 * t;
                T[(size_t)r * HDIM + perm(cc)]     = f2tf(acc[mi][ni][h * 2 + 0]);
                T[(size_t)r * HDIM + perm(cc + 1)] = f2tf(acc[mi][ni][h * 2 + 1]);
            }
        }
}

// ---------------------------------------------------------------------------
// attf_lite: phase-2 only. outs[64x256 packed swz] + tmp in 4 dbuf 64x64 chunks.
// logits = tmp @ outs^T + rank-1; promo; gather. 99KB smem -> 2 CTAs/SM.
// ---------------------------------------------------------------------------
constexpr int AL_TC    = 16384;       // tmp chunks: 2 x 4096 words
constexpr int AL_MISC  = 24576;       // uo64 + vo64 + offs32
constexpr int AL_WORDS = 24736;       // 98944 bytes

__global__ __launch_bounds__(256, 2)
void attf_kernel(const int* __restrict__ gidx, float* __restrict__ out) {
    extern __shared__ unsigned sh[];
    unsigned* outs = sh;
    unsigned* tc   = sh + AL_TC;
    float* uo   = (float*)(sh + AL_MISC);
    float* vo   = uo + 64;
    float* offs = vo + 64;
    float* fulls = (float*)sh;               // alias outs (dead after reads)

    const int b = blockIdx.x, tid = threadIdx.x;
    const unsigned* ob = g_out + (size_t)b * 64 * HDIM;
    const unsigned* tb = g_tmp + (size_t)b * 64 * HDIM;

    // G0: outs
#pragma unroll
    for (int i = 0; i < 16; i++) {
        int idx = tid + i * 256;
        int row = idx >> 6, c4 = (idx & 63) << 2;
        cpa16(sptr(&outs[row * 256 + (c4 ^ ((row & 3) << 3))]),
              ob + (size_t)row * HDIM + c4);
    }
    CPA_COMMIT;
    // G1, G2: tmp chunks 0, 1
#pragma unroll
    for (int q = 0; q < 2; q++) {
#pragma unroll
        for (int i = 0; i < 4; i++) {
            int idx = tid + i * 256;
            int r = idx >> 4, c4 = (idx & 15) << 2;
            cpa16(sptr(&tc[q * 4096 + r * 64 + (c4 ^ ((r & 3) << 3))]),
                  tb + (size_t)r * HDIM + q * 64 + c4);
        }
        CPA_COMMIT;
    }

    const int warp = tid >> 5, lane = tid & 31, g = lane >> 2, t = lane & 3;
    const int sw = (g & 3) << 3;
    const int wm2 = warp >> 1, wn2 = warp & 1;   // 16x32 tiles (4m x 2n)

    float acc2[4][4];
#pragma unroll
    for (int i = 0; i < 4; i++)
#pragma unroll
        for (int j = 0; j < 4; j++) acc2[i][j] = 0.f;

#pragma unroll
    for (int q = 0; q < 4; q++) {
        if (q < 3) { CPA_WAIT(1); } else { CPA_WAIT(0); }
        __syncthreads();
        const unsigned* tq = &tc[(q & 1) * 4096];
#pragma unroll
        for (int k8 = 0; k8 < 64; k8 += 8) {
            int r2 = wm2 * 16 + g;
            uint2 a0 = *(const uint2*)&tq[r2 * 64 + ((k8 + 2 * t) ^ sw)];
            uint2 a1 = *(const uint2*)&tq[(r2 + 8) * 64 + ((k8 + 2 * t) ^ sw)];
            unsigned a[4] = {a0.x, a1.x, a0.y, a1.y};
#pragma unroll
            for (int ni = 0; ni < 4; ni++) {
                int c = wn2 * 32 + ni * 8 + g;
                uint2 bv = *(const uint2*)&outs[c * 256 + ((q * 64 + k8 + 2 * t) ^ sw)];
                unsigned bb[2] = {bv.x, bv.y};
                mma8(acc2[ni], a, bb);
            }
        }
        __syncthreads();
        if (q < 2) {
            int qn = q + 2;
#pragma unroll
            for (int i = 0; i < 4; i++) {
                int idx = tid + i * 256;
                int r = idx >> 4, c4 = (idx & 15) << 2;
                cpa16(sptr(&tc[(q & 1) * 4096 + r * 64 + (c4 ^ ((r & 3) << 3))]),
                      tb + (size_t)r * HDIM + qn * 64 + c4);
            }
            CPA_COMMIT;
        }
    }

    // ---- rank-1 terms ----
    {
        int i = tid >> 2, part = tid & 3;
        int swi = (i & 3) << 3;
        const unsigned* orow = &outs[i * 256];
        float su = 0.f, sv = 0.f;
#pragma unroll 8
        for (int j = 0; j < 64; j++) {
            int pp = part * 64 + j;
            float ov = __uint_as_float(orow[pp ^ swi]);
            su += g_u[pp] * ov;
            sv += g_v[pp] * ov;
        }
        su += __shfl_down_sync(0xffffffffu, su, 2);
        su += __shfl_down_sync(0xffffffffu, su, 1);
        sv += __shfl_down_sync(0xffffffffu, sv, 2);
        sv += __shfl_down_sync(0xffffffffu, sv, 1);
        if (part == 0) { uo[i] = su; vo[i] = sv; }
    }
    {
        int pair = tid >> 3, l = tid & 7, p = pair >> 3, s = pair & 7;
        int swr = ((56 + s) & 3) << 3;
        const unsigned* kr = &outs[(56 + s) * 256];
        const float* wr = g_wp + p * HDIM;
        float sum = 0.f;
#pragma unroll 8
        for (int j = 0; j < 32; j++) {
            int pp = l + 8 * j;
            sum += __uint_as_float(kr[pp ^ swr]) * wr[pp];
        }
        sum += __shfl_down_sync(0xffffffffu, sum, 4);
        sum += __shfl_down_sync(0xffffffffu, sum, 2);
        sum += __shfl_down_sync(0xffffffffu, sum, 1);
        if (l == 0) offs[pair] = sum + g_misc[1 + p];
    }
    __syncthreads();   // all outs reads done -> fulls may overwrite

    const float s0v = g_misc[0];
#pragma unroll
    for (int ni = 0; ni < 4; ni++) {
        int cc = wn2 * 32 + ni * 8 + 2 * t;
        int r = wm2 * 16 + g;
        fulls[r * 64 + cc]           = (acc2[ni][0] + uo[r] + vo[cc] + s0v) * PSCALE;
        fulls[r * 64 + cc + 1]       = (acc2[ni][1] + uo[r] + vo[cc + 1] + s0v) * PSCALE;
        fulls[(r + 8) * 64 + cc]     = (acc2[ni][2] + uo[r + 8] + vo[cc] + s0v) * PSCALE;
        fulls[(r + 8) * 64 + cc + 1] = (acc2[ni][3] + uo[r + 8] + vo[cc + 1] + s0v) * PSCALE;
    }
    __syncthreads();

    if (tid < 192) {
        int qq = tid / 24, rr = tid % 24, s = rr / 3, p = rr % 3;
        fulls[4096 + tid] = offs[p * 8 + s] + offs[24 + s]
                          + fulls[(48 + qq) * 64 + 56 + s];
    }
    __syncthreads();

    float* obp = out + (size_t)b * 1858;
    for (int i = tid; i < 1858; i += 256) obp[i] = fulls[gidx[i]];
}

// ---------------------------------------------------------------------------
extern "C" void kernel_launch(void* const* d_in, const int* in_sizes, int n_in,
                              void* d_out, int out_size) {
    const float* x  = (const float*)d_in[0];
    const float* w1 = (const float*)d_in[1];
    const float* b1 = (const float*)d_in[2];
    const float* w2 = (const float*)d_in[3];
    const float* b2 = (const float*)d_in[4];
    const float* w3 = (const float*)d_in[5];
    const float* b3 = (const float*)d_in[6];
    const float* w4 = (const float*)d_in[7];
    const int*   gi = (const int*)d_in[8];
    float* out = (float*)d_out;

    const int M = in_sizes[0] / HDIM;     // 262144
    const int nblk = M / 64;              // 4096

    unsigned *o, *tm;
    cudaGetSymbolAddress((void**)&o, g_out);
    cudaGetSymbolAddress((void**)&tm, g_tmp);

    const int smemM = 2 * 256 * 68 * 4;                        // 139264
    const int smem1 = (2 * 128 * GSA + 2 * 128 * GSB) * 4;     // 77824
    const int smemT = 16384 * 4;                               // 65536
    const int smemA = AL_WORDS * 4;                            // 98944

    static bool init = false;
    if (!init) {
        cudaFuncSetAttribute((const void*)prepM_kernel,
                             cudaFuncAttributeMaxDynamicSharedMemorySize, smemM);
        cudaFuncSetAttribute((const void*)gemm1_kernel,
                             cudaFuncAttributeMaxDynamicSharedMemorySize, smem1);
        cudaFuncSetAttribute((const void*)gemmT_kernel,
                             cudaFuncAttributeMaxDynamicSharedMemorySize, smemT);
        cudaFuncSetAttribute((const void*)attf_kernel,
                             cudaFuncAttributeMaxDynamicSharedMemorySize, smemA);
        init = true;
    }

    prep_w1_kernel<<<HDIM * HDIM / 256, 256>>>(w1);
    prepM_kernel<<<16, 256, smemM>>>(w2, w3);
    prepv_kernel<<<1, 256>>>(w2, b2, w3, b3, w4);
    gemm1_kernel<<<dim3(2, M / 128), 256, smem1>>>(x, b1, o);
    gemmT_kernel<<<dim3(2, M / 128), 256, smemT>>>(tm);
    attf_kernel<<<nblk, 256, smemA>>>(gi, out);
}

// round 15
// speedup vs baseline: 1.1667x; 1.1667x over previous
#include <cuda_runtime.h>
#include <cstdint>
#include <cstddef>

// ---------------------------------------------------------------------------
// PolicyHead round 14 (= round 9 + conflict-free rank-1 reductions):
//   logits = out@M@out^T + u.out_i + v.out_j + s0,  M = W2^T W3 (precomputed)
//   attf v5: v4 with uo/vo/offs computed one-row-per-warp lane-striped
//   (bank-conflict-free; was 32-way-conflicted = 60% of crossbar traffic).
// ---------------------------------------------------------------------------

#define HDIM 256
#define MROWS 262144
#define PSCALE 0.0625f

__device__ unsigned g_out[(size_t)MROWS * HDIM];
__device__ unsigned g_w1[HDIM * HDIM];     // tf32 bits, perm'd k
__device__ unsigned g_mt[HDIM * HDIM];     // Mt[c,a], tf32, perm on a
__device__ float    g_u[HDIM];             // perm-indexed
__device__ float    g_v[HDIM];             // perm-indexed
__device__ float    g_wp[4 * HDIM];        // perm-indexed
__device__ float    g_misc[8];             // [0]=s0, [1..4]=d0[p]

__device__ __forceinline__ unsigned f2tf(float f) {
    unsigned r;
    asm("cvt.rna.tf32.f32 %0, %1;" : "=r"(r) : "f"(f));
    return r;
}
__device__ __forceinline__ int perm(int c) {
    return (c & ~7) | ((c & 3) << 1) | ((c >> 2) & 1);
}
__device__ __forceinline__ void mma8(float* d, const unsigned* a, const unsigned* b) {
    asm volatile(
        "mma.sync.aligned.m16n8k8.row.col.f32.tf32.tf32.f32 "
        "{%0,%1,%2,%3}, {%4,%5,%6,%7}, {%8,%9}, {%0,%1,%2,%3};\n"
        : "+f"(d[0]), "+f"(d[1]), "+f"(d[2]), "+f"(d[3])
        : "r"(a[0]), "r"(a[1]), "r"(a[2]), "r"(a[3]), "r"(b[0]), "r"(b[1]));
}
__device__ __forceinline__ unsigned sptr(const void* p) {
    return (unsigned)__cvta_generic_to_shared(p);
}
__device__ __forceinline__ void cpa16(unsigned s, const void* g) {
    asm volatile("cp.async.ca.shared.global [%0], [%1], 16;" :: "r"(s), "l"(g));
}
#define CPA_COMMIT asm volatile("cp.async.commit_group;")
#define CPA_WAIT(n) asm volatile("cp.async.wait_group %0;" :: "n"(n))

// ---------------------------------------------------------------------------
__global__ void prep_w1_kernel(const float* __restrict__ w1) {
    int i = blockIdx.x * 256 + threadIdx.x;
    int row = i >> 8, col = i & 255;
    g_w1[row * HDIM + perm(col)] = f2tf(w1[i]);
}

__global__ __launch_bounds__(256)
void prepM_kernel(const float* __restrict__ w2, const float* __restrict__ w3) {
    extern __shared__ float s[];
    float* s2 = s;               // [256][68]
    float* s3 = s + 256 * 68;
    const int a0 = (blockIdx.x & 3) * 64, c0 = (blockIdx.x >> 2) * 64;
    const int tid = threadIdx.x;
    for (int j = tid; j < 256 * 16; j += 256) {
        int h = j >> 4, q4 = (j & 15) << 2;
        *(float4*)&s2[h * 68 + q4] = *(const float4*)(w2 + h * HDIM + a0 + q4);
        *(float4*)&s3[h * 68 + q4] = *(const float4*)(w3 + h * HDIM + c0 + q4);
    }
    __syncthreads();
    const int tx = tid & 15, ty = tid >> 4;
    float acc[4][4] = {};
    for (int h = 0; h < 256; h++) {
        float4 av = *(float4*)&s2[h * 68 + tx * 4];
        float4 cv = *(float4*)&s3[h * 68 + ty * 4];
        float aa[4] = {av.x, av.y, av.z, av.w};
        float cc[4] = {cv.x, cv.y, cv.z, cv.w};
#pragma unroll
        for (int i = 0; i < 4; i++)
#pragma unroll
            for (int j = 0; j < 4; j++) acc[i][j] += cc[i] * aa[j];
    }
#pragma unroll
    for (int i = 0; i < 4; i++)
#pragma unroll
        for (int j = 0; j < 4; j++)
            g_mt[(c0 + ty * 4 + i) * HDIM + perm(a0 + tx * 4 + j)] = f2tf(acc[i][j]);
}

__global__ void prepv_kernel(const float* __restrict__ w2, const float* __restrict__ b2,
                             const float* __restrict__ w3, const float* __restrict__ b3,
                             const float* __restrict__ w4) {
    int a = threadIdx.x;
    float u = 0.f, v = 0.f, p0 = 0.f, p1 = 0.f, p2 = 0.f, p3 = 0.f;
    for (int h = 0; h < 256; h++) {
        float w2v = w2[h * HDIM + a], w3v = w3[h * HDIM + a];
        u += w2v * b3[h];
        v += b2[h] * w3v;
        p0 += w3v * w4[0 * HDIM + h];
        p1 += w3v * w4[1 * HDIM + h];
        p2 += w3v * w4[2 * HDIM + h];
        p3 += w3v * w4[3 * HDIM + h];
    }
    int pa = perm(a);
    g_u[pa] = u; g_v[pa] = v;
    g_wp[0 * HDIM + pa] = p0; g_wp[1 * HDIM + pa] = p1;
    g_wp[2 * HDIM + pa] = p2; g_wp[3 * HDIM + pa] = p3;
    if (a == 0) {
        float s = 0.f;
        for (int h = 0; h < 256; h++) s += b2[h] * b3[h];
        g_misc[0] = s;
    }
    if (a >= 1 && a <= 4) {
        float d = 0.f;
        for (int h = 0; h < 256; h++) d += b3[h] * w4[(a - 1) * HDIM + h];
        g_misc[a] = d;
    }
}

// ---------------------------------------------------------------------------
// GEMM1 (round-5, proven 255us): out = relu(x @ W1^T + b1).
// ---------------------------------------------------------------------------
constexpr int GSA = 36;
constexpr int GSB = 40;

__global__ __launch_bounds__(256, 2)
void gemm1_kernel(const float* __restrict__ A, const float* __restrict__ bias,
                  unsigned* __restrict__ C) {
    extern __shared__ unsigned sh[];
    unsigned* sA = sh;
    unsigned* sB = sh + 2 * 128 * GSA;
    const int m0 = blockIdx.y * 128, n0 = blockIdx.x * 128;
    const int tid = threadIdx.x;
    const int warp = tid >> 5, lane = tid & 31, g = lane >> 2, t = lane & 3;
    const int wm = warp >> 1, wn = warp & 1;

    float acc[2][8][4];
#pragma unroll
    for (int i = 0; i < 2; i++)
#pragma unroll
        for (int j = 0; j < 8; j++)
#pragma unroll
            for (int l = 0; l < 4; l++) acc[i][j][l] = 0.f;

    const int lrow = tid >> 3, lc4 = (tid & 7) << 2;

#pragma unroll
    for (int i = 0; i < 4; i++) {
        int row = lrow + i * 32;
        cpa16(sptr(&sA[row * GSA + lc4]), A + (size_t)(m0 + row) * HDIM + lc4);
        cpa16(sptr(&sB[row * GSB + lc4]), g_w1 + (size_t)(n0 + row) * HDIM + lc4);
    }
    CPA_COMMIT;

    for (int c = 0; c < 8; c++) {
        int cur = c & 1;
        if (c < 7) {
            int nx = cur ^ 1, k0 = (c + 1) * 32;
#pragma unroll
            for (int i = 0; i < 4; i++) {
                int row = lrow + i * 32;
                cpa16(sptr(&sA[nx * 128 * GSA + row * GSA + lc4]),
                      A + (size_t)(m0 + row) * HDIM + k0 + lc4);
                cpa16(sptr(&sB[nx * 128 * GSB + row * GSB + lc4]),
                      g_w1 + (size_t)(n0 + row) * HDIM + k0 + lc4);
            }
            CPA_COMMIT;
            CPA_WAIT(1);
        } else {
            CPA_WAIT(0);
        }
        __syncthreads();
        const unsigned* As = &sA[cur * 128 * GSA];
        const unsigned* Bs = &sB[cur * 128 * GSB];
#pragma unroll
        for (int ks = 0; ks < 32; ks += 8) {
            unsigned a[2][4];
#pragma unroll
            for (int mi = 0; mi < 2; mi++) {
                int r = wm * 32 + mi * 16;
                a[mi][0] = f2tf(__uint_as_float(As[(r + g) * GSA + ks + t]));
                a[mi][1] = f2tf(__uint_as_float(As[(r + g + 8) * GSA + ks + t]));
                a[mi][2] = f2tf(__uint_as_float(As[(r + g) * GSA + ks + t + 4]));
                a[mi][3] = f2tf(__uint_as_float(As[(r + g + 8) * GSA + ks + t + 4]));
            }
#pragma unroll
            for (int ni = 0; ni < 8; ni++) {
                int cc = wn * 64 + ni * 8;
                uint2 bv = *(const uint2*)&Bs[(cc + g) * GSB + ks + 2 * t];
                unsigned bb[2] = {bv.x, bv.y};
                mma8(acc[0][ni], a[0], bb);
                mma8(acc[1][ni], a[1], bb);
            }
        }
        __syncthreads();
    }
#pragma unroll
    for (int mi = 0; mi < 2; mi++)
#pragma unroll
        for (int h = 0; h < 2; h++) {
            int r = m0 + wm * 32 + mi * 16 + g + h * 8;
#pragma unroll
            for (int ni = 0; ni < 8; ni++) {
                int cc = n0 + wn * 64 + ni * 8 + 2 * t;
                float v0 = fmaxf(acc[mi][ni][h * 2 + 0] + bias[cc], 0.f);
                float v1 = fmaxf(acc[mi][ni][h * 2 + 1] + bias[cc + 1], 0.f);
                C[(size_t)r * HDIM + perm(cc)]     = f2tf(v0);
                C[(size_t)r * HDIM + perm(cc + 1)] = f2tf(v1);
            }
        }
}

// ---------------------------------------------------------------------------
// attf v5: v4 (tmp-in-registers, XOR-swizzled packed smem, 2 CTAs/SM) with
// conflict-free rank-1 reductions (one row per warp, lane-striped).
// ---------------------------------------------------------------------------
constexpr int A4_OUTS  = 0;           // 64*256 = 16384 words
constexpr int A4_MT    = 16384;       // 256*32 = 8192 words (qtmp: 64*64 alias)
constexpr int A4_MISC  = 24576;       // uo64 + vo64 + offs32 = 160
constexpr int A4_WORDS = 24736;       // 98944 bytes

__global__ __launch_bounds__(256, 2)
void attf_kernel(const int* __restrict__ gidx, float* __restrict__ out) {
    extern __shared__ unsigned sh[];
    unsigned* outs = sh + A4_OUTS;
    unsigned* mt   = sh + A4_MT;
    unsigned* qtmp = mt;                     // alias: mt dead after phase 1
    float* uo   = (float*)(sh + A4_MISC);
    float* vo   = uo + 64;
    float* offs = vo + 64;
    float* fulls = (float*)sh;               // alias outs (dead after reads)

    const int b = blockIdx.x, tid = threadIdx.x;
    const unsigned* ob = g_out + (size_t)b * 64 * HDIM;

    // prologue: outs (packed+swizzled) + Mt stage 0
#pragma unroll
    for (int i = 0; i < 16; i++) {
        int idx = tid + i * 256;
        int row = idx >> 6, c4 = (idx & 63) << 2;
        cpa16(sptr(&outs[row * 256 + (c4 ^ ((row & 3) << 3))]),
              ob + (size_t)row * HDIM + c4);
    }
#pragma unroll
    for (int i = 0; i < 8; i++) {
        int e = tid + i * 256;
        int r = e >> 3, c4 = (e & 7) << 2;
        cpa16(sptr(&mt[r * 32 + (c4 ^ ((r & 3) << 3))]),
              g_mt + (size_t)r * HDIM + c4);
    }
    CPA_COMMIT;

    const int warp = tid >> 5, lane = tid & 31, g = lane >> 2, t = lane & 3;
    const int sw = (g & 3) << 3;
    const int wm = warp >> 2, wn = warp & 3;     // phase 1: 32x64 tiles
    const int wm2 = warp >> 1, wn2 = warp & 1;   // phase 2: 16x32 tiles

    float acc[2][8][4];
#pragma unroll
    for (int i = 0; i < 2; i++)
#pragma unroll
        for (int j = 0; j < 8; j++)
#pragma unroll
            for (int l = 0; l < 4; l++) acc[i][j][l] = 0.f;

    // ---- phase 1: tmp = outs @ Mt^T, accumulated fully in registers ----
    for (int s = 0; s < 8; s++) {
        CPA_WAIT(0);
        __syncthreads();
        const int kb = s * 32;
#pragma unroll
        for (int ks = 0; ks < 32; ks += 8) {
            unsigned a[2][4];
#pragma unroll
            for (int mi = 0; mi < 2; mi++) {
                int r0 = wm * 32 + mi * 16 + g;
                uint2 a0 = *(const uint2*)&outs[r0 * 256 + ((kb + ks + 2 * t) ^ sw)];
                uint2 a1 = *(const uint2*)&outs[(r0 + 8) * 256 + ((kb + ks + 2 * t) ^ sw)];
                a[mi][0] = a0.x; a[mi][1] = a1.x; a[mi][2] = a0.y; a[mi][3] = a1.y;
            }
#pragma unroll
            for (int ni = 0; ni < 8; ni++) {
                int c = wn * 64 + ni * 8 + g;
                uint2 bv = *(const uint2*)&mt[c * 32 + ((ks + 2 * t) ^ sw)];
                unsigned bb[2] = {bv.x, bv.y};
                mma8(acc[0][ni], a[0], bb);
                mma8(acc[1][ni], a[1], bb);
            }
        }
        __syncthreads();
        if (s < 7) {
            const int kn = (s + 1) * 32;
#pragma unroll
            for (int i = 0; i < 8; i++) {
                int e = tid + i * 256;
                int r = e >> 3, c4 = (e & 7) << 2;
                cpa16(sptr(&mt[r * 32 + (c4 ^ ((r & 3) << 3))]),
                      g_mt + (size_t)r * HDIM + kn + c4);
            }
            CPA_COMMIT;
        }
    }

    // ---- phase 2: logits = tmp @ outs^T via 4 q-passes through qtmp ----
    float acc2[4][4];
#pragma unroll
    for (int i = 0; i < 4; i++)
#pragma unroll
        for (int j = 0; j < 4; j++) acc2[i][j] = 0.f;

    for (int q = 0; q < 4; q++) {
        __syncthreads();   // prior q reads (or phase-1 mt reads) complete
        if (wn == q) {
#pragma unroll
            for (int mi = 0; mi < 2; mi++)
#pragma unroll
                for (int ni = 0; ni < 8; ni++) {
                    int lc = ni * 8 + 2 * t;
                    int lp0 = (lc & ~7) | ((lc & 3) << 1) | ((lc >> 2) & 1);
                    int lc1 = lc + 1;
                    int lp1 = (lc1 & ~7) | ((lc1 & 3) << 1) | ((lc1 >> 2) & 1);
                    int r = wm * 32 + mi * 16 + g;
                    qtmp[r * 64 + (lp0 ^ sw)]       = f2tf(acc[mi][ni][0]);
                    qtmp[r * 64 + (lp1 ^ sw)]       = f2tf(acc[mi][ni][1]);
                    qtmp[(r + 8) * 64 + (lp0 ^ sw)] = f2tf(acc[mi][ni][2]);
                    qtmp[(r + 8) * 64 + (lp1 ^ sw)] = f2tf(acc[mi][ni][3]);
                }
        }
        __syncthreads();
#pragma unroll
        for (int k8 = 0; k8 < 64; k8 += 8) {
            int r2 = wm2 * 16 + g;
            uint2 a0 = *(const uint2*)&qtmp[r2 * 64 + ((k8 + 2 * t) ^ sw)];
            uint2 a1 = *(const uint2*)&qtmp[(r2 + 8) * 64 + ((k8 + 2 * t) ^ sw)];
            unsigned a[4] = {a0.x, a1.x, a0.y, a1.y};
#pragma unroll
            for (int ni = 0; ni < 4; ni++) {
                int c = wn2 * 32 + ni * 8 + g;
                uint2 bv = *(const uint2*)&outs[c * 256 + ((q * 64 + k8 + 2 * t) ^ sw)];
                unsigned bb[2] = {bv.x, bv.y};
                mma8(acc2[ni], a, bb);
            }
        }
    }

    // ---- rank-1 terms: one row per warp, lane-striped (conflict-free) ----
    {
        // uo[r] = u.out_r ; vo[r] = v.out_r    (warp w -> rows 8w..8w+7)
#pragma unroll
        for (int rr = 0; rr < 8; rr++) {
            int r = warp * 8 + rr;
            int swr = (r & 3) << 3;
            const unsigned* orow = &outs[r * 256];
            float su = 0.f, sv = 0.f;
#pragma unroll
            for (int j = 0; j < 8; j++) {
                int pp = lane + 32 * j;
                float ov = __uint_as_float(orow[pp ^ swr]);
                su += g_u[pp] * ov;
                sv += g_v[pp] * ov;
            }
#pragma unroll
            for (int d = 16; d > 0; d >>= 1) {
                su += __shfl_down_sync(0xffffffffu, su, d);
                sv += __shfl_down_sync(0xffffffffu, sv, d);
            }
            if (lane == 0) { uo[r] = su; vo[r] = sv; }
        }
    }
    {
        // offs[p*8+s] = out_{56+s} . wp[p] + d0[p]    (warp w -> s = w)
        int s = warp;
        int r = 56 + s, swr = (r & 3) << 3;
        const unsigned* kr = &outs[r * 256];
#pragma unroll
        for (int p = 0; p < 4; p++) {
            const float* wr = g_wp + p * HDIM;
            float sum = 0.f;
#pragma unroll
            for (int j = 0; j < 8; j++) {
                int pp = lane + 32 * j;
                sum += __uint_as_float(kr[pp ^ swr]) * wr[pp];
            }
#pragma unroll
            for (int d = 16; d > 0; d >>= 1)
                sum += __shfl_down_sync(0xffffffffu, sum, d);
            if (lane == 0) offs[p * 8 + s] = sum + g_misc[1 + p];
        }
    }
    __syncthreads();   // all outs reads done -> fulls may overwrite

    const float s0v = g_misc[0];
#pragma unroll
    for (int ni = 0; ni < 4; ni++) {
        int cc = wn2 * 32 + ni * 8 + 2 * t;
        int r = wm2 * 16 + g;
        fulls[r * 64 + cc]           = (acc2[ni][0] + uo[r] + vo[cc] + s0v) * PSCALE;
        fulls[r * 64 + cc + 1]       = (acc2[ni][1] + uo[r] + vo[cc + 1] + s0v) * PSCALE;
        fulls[(r + 8) * 64 + cc]     = (acc2[ni][2] + uo[r + 8] + vo[cc] + s0v) * PSCALE;
        fulls[(r + 8) * 64 + cc + 1] = (acc2[ni][3] + uo[r + 8] + vo[cc + 1] + s0v) * PSCALE;
    }
    __syncthreads();

    if (tid < 192) {
        int qq = tid / 24, rr = tid % 24, s = rr / 3, p = rr % 3;
        fulls[4096 + tid] = offs[p * 8 + s] + offs[24 + s]
                          + fulls[(48 + qq) * 64 + 56 + s];
    }
    __syncthreads();

    float* obp = out + (size_t)b * 1858;
    for (int i = tid; i < 1858; i += 256) obp[i] = fulls[gidx[i]];
}

// ---------------------------------------------------------------------------
extern "C" void kernel_launch(void* const* d_in, const int* in_sizes, int n_in,
                              void* d_out, int out_size) {
    const float* x  = (const float*)d_in[0];
    const float* w1 = (const float*)d_in[1];
    const float* b1 = (const float*)d_in[2];
    const float* w2 = (const float*)d_in[3];
    const float* b2 = (const float*)d_in[4];
    const float* w3 = (const float*)d_in[5];
    const float* b3 = (const float*)d_in[6];
    const float* w4 = (const float*)d_in[7];
    const int*   gi = (const int*)d_in[8];
    float* out = (float*)d_out;

    const int M = in_sizes[0] / HDIM;     // 262144
    const int nblk = M / 64;              // 4096

    unsigned* o;
    cudaGetSymbolAddress((void**)&o, g_out);

    const int smemM = 2 * 256 * 68 * 4;                        // 139264
    const int smem1 = (2 * 128 * GSA + 2 * 128 * GSB) * 4;     // 77824
    const int smemA = A4_WORDS * 4;                            // 98944

    static bool init = false;
    if (!init) {
        cudaFuncSetAttribute((const void*)prepM_kernel,
                             cudaFuncAttributeMaxDynamicSharedMemorySize, smemM);
        cudaFuncSetAttribute((const void*)gemm1_kernel,
                             cudaFuncAttributeMaxDynamicSharedMemorySize, smem1);
        cudaFuncSetAttribute((const void*)attf_kernel,
                             cudaFuncAttributeMaxDynamicSharedMemorySize, smemA);
        init = true;
    }

    prep_w1_kernel<<<HDIM * HDIM / 256, 256>>>(w1);
    prepM_kernel<<<16, 256, smemM>>>(w2, w3);
    prepv_kernel<<<1, 256>>>(w2, b2, w3, b3, w4);
    gemm1_kernel<<<dim3(2, M / 128), 256, smem1>>>(x, b1, o);
    attf_kernel<<<nblk, 256, smemA>>>(gi, out);
}